// round 1
// baseline (speedup 1.0000x reference)
#include <cuda_runtime.h>
#include <math.h>

#define N_NODES  100000
#define N_EDGES  3200000
#define N_GRAPHS 64
#define SCAN_CHUNK 512
#define SCAN_BLOCKS ((N_NODES + SCAN_CHUNK - 1) / SCAN_CHUNK)   // 196

// ---------------- scratch (device globals; no runtime allocation) ----------
__device__ int   g_deg [N_NODES];
__device__ int   g_fill[N_NODES];
__device__ int   g_off [N_NODES];
__device__ int   g_bsum[SCAN_BLOCKS];
__device__ float g_dinv[N_NODES];
__device__ int   g_src [N_EDGES];
__device__ float g_coef[N_EDGES];
__device__ float g_h   [N_NODES * 128];
__device__ float g_a   [N_NODES * 128];
__device__ float g_pool[N_GRAPHS * 128];
__device__ float g_cnt [N_GRAPHS];
__device__ float g_z   [N_GRAPHS * 64];

// ---------------- prep kernels ---------------------------------------------
__global__ void k_zero()
{
    int tid = blockIdx.x * blockDim.x + threadIdx.x;
    int stride = gridDim.x * blockDim.x;
    for (int i = tid; i < N_NODES; i += stride) { g_deg[i] = 0; g_fill[i] = 0; }
    for (int i = tid; i < N_GRAPHS * 128; i += stride) g_pool[i] = 0.f;
    for (int i = tid; i < N_GRAPHS; i += stride) g_cnt[i] = 0.f;
}

__global__ void k_deg(const int* __restrict__ dst)
{
    int tid = blockIdx.x * blockDim.x + threadIdx.x;
    int stride = gridDim.x * blockDim.x;
    for (int e = tid; e < N_EDGES; e += stride)
        atomicAdd(&g_deg[dst[e]], 1);
}

__global__ void k_scan1()
{
    __shared__ int s[SCAN_CHUNK];
    int i = blockIdx.x * SCAN_CHUNK + threadIdx.x;
    int v = (i < N_NODES) ? g_deg[i] : 0;
    s[threadIdx.x] = v;
    __syncthreads();
    for (int off = 1; off < SCAN_CHUNK; off <<= 1) {
        int t = (threadIdx.x >= off) ? s[threadIdx.x - off] : 0;
        __syncthreads();
        s[threadIdx.x] += t;
        __syncthreads();
    }
    if (i < N_NODES) g_off[i] = s[threadIdx.x] - v;   // exclusive within block
    if (threadIdx.x == SCAN_CHUNK - 1) g_bsum[blockIdx.x] = s[SCAN_CHUNK - 1];
}

__global__ void k_scan2()
{
    if (threadIdx.x == 0 && blockIdx.x == 0) {
        int run = 0;
        for (int b = 0; b < SCAN_BLOCKS; b++) {
            int t = g_bsum[b];
            g_bsum[b] = run;
            run += t;
        }
    }
}

__global__ void k_scan3()
{
    int i = blockIdx.x * blockDim.x + threadIdx.x;
    if (i < N_NODES) {
        g_off[i] += g_bsum[i / SCAN_CHUNK];
        g_dinv[i] = rsqrtf((float)g_deg[i] + 1.0f);
    }
}

__global__ void k_fill(const int* __restrict__ src, const int* __restrict__ dst)
{
    int tid = blockIdx.x * blockDim.x + threadIdx.x;
    int stride = gridDim.x * blockDim.x;
    for (int e = tid; e < N_EDGES; e += stride) {
        int s = src[e];
        int d = dst[e];
        int p = atomicAdd(&g_fill[d], 1);
        int idx = g_off[d] + p;
        g_src[idx]  = s;
        g_coef[idx] = g_dinv[s] * g_dinv[d];
    }
}

// ---------------- fused two-tower node matmul ------------------------------
// h[n, 0:DOUTH]       = in_mu_part(n)  @ Wm
// h[n, DOUTH:2*DOUTH] = in_log_part(n) @ Wl
template<int DIN, int DOUTH, bool SHARED_IN>
__global__ void k_mm(const float* __restrict__ in,
                     const float* __restrict__ Wm,
                     const float* __restrict__ Wl,
                     float* __restrict__ h)
{
    const int DTOT = 2 * DOUTH;
    const int IN_STRIDE = SHARED_IN ? DIN : 2 * DIN;
    __shared__ float Ws[2 * DIN * DOUTH];
    for (int i = threadIdx.x; i < DIN * DOUTH; i += blockDim.x) {
        Ws[i] = Wm[i];
        Ws[DIN * DOUTH + i] = Wl[i];
    }
    __syncthreads();
    int tid = blockIdx.x * blockDim.x + threadIdx.x;
    const int total = N_NODES * DTOT;
    int stride = gridDim.x * blockDim.x;
    for (; tid < total; tid += stride) {
        int n = tid / DTOT;
        int j = tid - n * DTOT;
        int tower = (j >= DOUTH) ? 1 : 0;
        int jj = tower ? (j - DOUTH) : j;
        const float* W = Ws + tower * DIN * DOUTH;
        const float* row = in + n * IN_STRIDE + (SHARED_IN ? 0 : tower * DIN);
        float acc = 0.f;
        #pragma unroll
        for (int k = 0; k < DIN; k++)
            acc += row[k] * W[k * DOUTH + jj];
        h[tid] = acc;
    }
}

// ---------------- CSR gather aggregation + self-loop + bias + relu ---------
template<int DTOT>
__global__ void k_agg(const float* __restrict__ h,
                      const float* __restrict__ bm,
                      const float* __restrict__ bl,
                      float* __restrict__ out)
{
    const int R = DTOT / 32;
    int gwarp  = (blockIdx.x * blockDim.x + threadIdx.x) >> 5;
    int lane   = threadIdx.x & 31;
    int nwarps = (gridDim.x * blockDim.x) >> 5;
    for (int n = gwarp; n < N_NODES; n += nwarps) {
        float acc[R];
        #pragma unroll
        for (int r = 0; r < R; r++) acc[r] = 0.f;
        int start = g_off[n];
        int cnt   = g_deg[n];
        for (int e = 0; e < cnt; e++) {
            int   s = g_src[start + e];
            float c = g_coef[start + e];
            const float* hs = h + (size_t)s * DTOT + lane;
            #pragma unroll
            for (int r = 0; r < R; r++)
                acc[r] += c * hs[32 * r];
        }
        float di = g_dinv[n];
        float d2 = di * di;
        #pragma unroll
        for (int r = 0; r < R; r++) {
            int col = lane + 32 * r;
            float b = (col < DTOT / 2) ? bm[col] : bl[col - DTOT / 2];
            float v = acc[r] + h[(size_t)n * DTOT + col] * d2 + b;
            out[(size_t)n * DTOT + col] = fmaxf(v, 0.f);
        }
    }
}

// ---------------- segmented mean pool (batch is sorted) --------------------
__global__ void k_pool(const float* __restrict__ a, const int* __restrict__ batch)
{
    // blockDim.x == 128 (one thread per combined feature dim); 64 nodes/block
    int n0 = blockIdx.x * 64;
    if (n0 >= N_NODES) return;
    int j = threadIdx.x;
    int nend = min(n0 + 64, N_NODES);
    int gcur = batch[n0];
    float acc = 0.f, cacc = 0.f;
    for (int n = n0; n < nend; n++) {
        int g = batch[n];
        if (g != gcur) {
            atomicAdd(&g_pool[gcur * 128 + j], acc);
            if (j == 0) atomicAdd(&g_cnt[gcur], cacc);
            acc = 0.f; cacc = 0.f; gcur = g;
        }
        acc += a[(size_t)n * 128 + j];
        cacc += 1.f;
    }
    atomicAdd(&g_pool[gcur * 128 + j], acc);
    if (j == 0) atomicAdd(&g_cnt[gcur], cacc);
}

// ---------------- latent: mu/logvar means, reparameterized z ---------------
__global__ void k_latent(const float* __restrict__ eps, float* __restrict__ out)
{
    int tid = blockIdx.x * blockDim.x + threadIdx.x;
    if (tid >= N_GRAPHS * 64) return;
    int g = tid >> 6;
    int j = tid & 63;
    float cnt = fmaxf(g_cnt[g], 1.f);
    float mu = g_pool[g * 128 + j] / cnt;
    float lv = g_pool[g * 128 + 64 + j] / cnt;
    out[10240000 + tid] = mu;                    // mu block
    out[10240000 + 4096 + tid] = lv;             // logvar block
    g_z[tid] = mu + eps[tid] * expf(0.5f * lv);
}

// ---------------- decoder: sigmoid(z @ Wfc + bfc) --------------------------
__global__ void __launch_bounds__(256)
k_decode(const float* __restrict__ Wfc, const float* __restrict__ bfc,
         float* __restrict__ out)
{
    __shared__ float zs[N_GRAPHS * 64];
    for (int i = threadIdx.x; i < N_GRAPHS * 64; i += blockDim.x)
        zs[i] = g_z[i];
    __syncthreads();
    int j = blockIdx.x * blockDim.x + threadIdx.x;
    if (j >= 160000) return;
    float acc[N_GRAPHS];
    #pragma unroll
    for (int g = 0; g < N_GRAPHS; g++) acc[g] = 0.f;
    for (int k = 0; k < 64; k++) {
        float w = Wfc[(size_t)k * 160000 + j];
        #pragma unroll
        for (int g = 0; g < N_GRAPHS; g++)
            acc[g] += zs[g * 64 + k] * w;
    }
    float b = bfc[j];
    #pragma unroll
    for (int g = 0; g < N_GRAPHS; g++) {
        float v = acc[g] + b;
        out[(size_t)g * 160000 + j] = 1.f / (1.f + expf(-v));
    }
}

// ---------------- launch ---------------------------------------------------
extern "C" void kernel_launch(void* const* d_in, const int* in_sizes, int n_in,
                              void* d_out, int out_size)
{
    const float* x     = (const float*)d_in[0];
    const int*   ei    = (const int*)  d_in[1];
    const int*   batch = (const int*)  d_in[2];
    const float* W1m = (const float*)d_in[3];
    const float* b1m = (const float*)d_in[4];
    const float* W2m = (const float*)d_in[5];
    const float* b2m = (const float*)d_in[6];
    const float* W3m = (const float*)d_in[7];
    const float* b3m = (const float*)d_in[8];
    const float* W1l = (const float*)d_in[9];
    const float* b1l = (const float*)d_in[10];
    const float* W2l = (const float*)d_in[11];
    const float* b2l = (const float*)d_in[12];
    const float* W3l = (const float*)d_in[13];
    const float* b3l = (const float*)d_in[14];
    const float* Wfc = (const float*)d_in[15];
    const float* bfc = (const float*)d_in[16];
    const float* eps = (const float*)d_in[17];
    float* out = (float*)d_out;

    const int* src = ei;
    const int* dst = ei + N_EDGES;

    // structure prep
    k_zero<<<256, 256>>>();
    k_deg<<<2048, 256>>>(dst);
    k_scan1<<<SCAN_BLOCKS, SCAN_CHUNK>>>();
    k_scan2<<<1, 32>>>();
    k_scan3<<<(N_NODES + 255) / 256, 256>>>();
    k_fill<<<2048, 256>>>(src, dst);

    // layer 1: x[N,64] -> h[N,32] -> a[N,32]
    k_mm<64, 16, true><<<(N_NODES * 32 + 255) / 256, 256>>>(x, W1m, W1l, g_h);
    k_agg<32><<<(N_NODES * 32 + 255) / 256, 256>>>(g_h, b1m, b1l, g_a);

    // layer 2: a[N,32] -> h[N,64] -> a[N,64]
    k_mm<16, 32, false><<<(N_NODES * 64 + 255) / 256, 256>>>(g_a, W2m, W2l, g_h);
    k_agg<64><<<(N_NODES * 32 + 255) / 256, 256>>>(g_h, b2m, b2l, g_a);

    // layer 3: a[N,64] -> h[N,128] -> a[N,128]
    k_mm<32, 64, false><<<(N_NODES * 128 + 255) / 256, 256>>>(g_a, W3m, W3l, g_h);
    k_agg<128><<<(N_NODES * 32 + 255) / 256, 256>>>(g_h, b3m, b3l, g_a);

    // pool + latent + decode
    k_pool<<<(N_NODES + 63) / 64, 128>>>(g_a, batch);
    k_latent<<<(N_GRAPHS * 64 + 255) / 256, 256>>>(eps, out);
    k_decode<<<(160000 + 255) / 256, 256>>>(Wfc, bfc, out);
}

// round 3
// speedup vs baseline: 2.2615x; 2.2615x over previous
#include <cuda_runtime.h>
#include <math.h>

#define N_NODES  100000
#define N_EDGES  3200000
#define N_GRAPHS 64
#define SCAN_CHUNK 512
#define SCAN_BLOCKS ((N_NODES + SCAN_CHUNK - 1) / SCAN_CHUNK)   // 196

// ---------------- scratch (device globals; no runtime allocation) ----------
__device__ int   g_deg [N_NODES];
__device__ int   g_fill[N_NODES];
__device__ int   g_off [N_NODES];
__device__ int   g_bsum[SCAN_BLOCKS];
__device__ float g_dinv[N_NODES];
__device__ int   g_src [N_EDGES];
__device__ float g_coef[N_EDGES];
__device__ float g_t   [N_NODES * 64];    // aggregated inputs (pre-matmul)
__device__ float g_a   [N_NODES * 128];   // layer activations
__device__ float g_pool[N_GRAPHS * 128];
__device__ float g_cnt [N_GRAPHS];
__device__ float g_z   [N_GRAPHS * 64];

// ---------------- prep kernels ---------------------------------------------
__global__ void k_zero()
{
    int tid = blockIdx.x * blockDim.x + threadIdx.x;
    int stride = gridDim.x * blockDim.x;
    for (int i = tid; i < N_NODES; i += stride) { g_deg[i] = 0; g_fill[i] = 0; }
    for (int i = tid; i < N_GRAPHS * 128; i += stride) g_pool[i] = 0.f;
    for (int i = tid; i < N_GRAPHS; i += stride) g_cnt[i] = 0.f;
}

__global__ void k_deg(const int* __restrict__ dst)
{
    int tid = blockIdx.x * blockDim.x + threadIdx.x;
    int stride = gridDim.x * blockDim.x;
    for (int e = tid; e < N_EDGES; e += stride)
        atomicAdd(&g_deg[dst[e]], 1);
}

__global__ void k_scan1()
{
    __shared__ int s[SCAN_CHUNK];
    int i = blockIdx.x * SCAN_CHUNK + threadIdx.x;
    int v = (i < N_NODES) ? g_deg[i] : 0;
    s[threadIdx.x] = v;
    __syncthreads();
    for (int off = 1; off < SCAN_CHUNK; off <<= 1) {
        int t = (threadIdx.x >= off) ? s[threadIdx.x - off] : 0;
        __syncthreads();
        s[threadIdx.x] += t;
        __syncthreads();
    }
    if (i < N_NODES) g_off[i] = s[threadIdx.x] - v;   // exclusive within block
    if (threadIdx.x == SCAN_CHUNK - 1) g_bsum[blockIdx.x] = s[SCAN_CHUNK - 1];
}

// fused: add block-prefix (computed per-block from g_bsum) + dinv
__global__ void k_scan23()
{
    __shared__ int sb[256];
    int b = blockIdx.x;
    int t = threadIdx.x;
    if (t < 256) sb[t] = (t < b && t < SCAN_BLOCKS) ? g_bsum[t] : 0;
    __syncthreads();
    for (int off = 128; off > 0; off >>= 1) {
        if (t < off) sb[t] += sb[t + off];
        __syncthreads();
    }
    int prefix = sb[0];
    int i = b * SCAN_CHUNK + t;
    if (i < N_NODES) {
        g_off[i] += prefix;
        g_dinv[i] = rsqrtf((float)g_deg[i] + 1.0f);
    }
}

__global__ void k_fill(const int* __restrict__ src, const int* __restrict__ dst)
{
    int tid = blockIdx.x * blockDim.x + threadIdx.x;
    int stride = gridDim.x * blockDim.x;
    for (int e = tid; e < N_EDGES; e += stride) {
        int s = src[e];
        int d = dst[e];
        int p = atomicAdd(&g_fill[d], 1);
        int idx = g_off[d] + p;
        g_src[idx]  = s;
        g_coef[idx] = g_dinv[s] * g_dinv[d];
    }
}

// ---------------- CSR gather aggregation over INPUT features ---------------
// t[n] = sum_{s in N(n)} coef * in[s] + dinv[n]^2 * in[n]
template<int DIN>
__global__ void __launch_bounds__(256)
k_agg(const float* __restrict__ in, float* __restrict__ tout)
{
    int gwarp  = (blockIdx.x * blockDim.x + threadIdx.x) >> 5;
    int lane   = threadIdx.x & 31;
    int nwarps = (gridDim.x * blockDim.x) >> 5;
    for (int n = gwarp; n < N_NODES; n += nwarps) {
        int start = g_off[n];
        int cnt   = g_deg[n];
        const int*   __restrict__ sp = g_src  + start;
        const float* __restrict__ cp = g_coef + start;
        if (DIN == 64) {
            float ax = 0.f, ay = 0.f;
            int e = 0;
            for (; e + 4 <= cnt; e += 4) {
                int s0 = sp[e], s1 = sp[e+1], s2 = sp[e+2], s3 = sp[e+3];
                float c0 = cp[e], c1 = cp[e+1], c2 = cp[e+2], c3 = cp[e+3];
                float2 v0 = *(const float2*)(in + (size_t)s0 * 64 + lane * 2);
                float2 v1 = *(const float2*)(in + (size_t)s1 * 64 + lane * 2);
                float2 v2 = *(const float2*)(in + (size_t)s2 * 64 + lane * 2);
                float2 v3 = *(const float2*)(in + (size_t)s3 * 64 + lane * 2);
                ax += c0 * v0.x; ay += c0 * v0.y;
                ax += c1 * v1.x; ay += c1 * v1.y;
                ax += c2 * v2.x; ay += c2 * v2.y;
                ax += c3 * v3.x; ay += c3 * v3.y;
            }
            for (; e < cnt; e++) {
                int s = sp[e]; float c = cp[e];
                float2 v = *(const float2*)(in + (size_t)s * 64 + lane * 2);
                ax += c * v.x; ay += c * v.y;
            }
            float d = g_dinv[n]; float d2 = d * d;
            float2 vn = *(const float2*)(in + (size_t)n * 64 + lane * 2);
            ax += d2 * vn.x; ay += d2 * vn.y;
            *(float2*)(tout + (size_t)n * 64 + lane * 2) = make_float2(ax, ay);
        } else { // DIN == 32
            float a = 0.f;
            int e = 0;
            for (; e + 4 <= cnt; e += 4) {
                int s0 = sp[e], s1 = sp[e+1], s2 = sp[e+2], s3 = sp[e+3];
                float c0 = cp[e], c1 = cp[e+1], c2 = cp[e+2], c3 = cp[e+3];
                float v0 = in[(size_t)s0 * 32 + lane];
                float v1 = in[(size_t)s1 * 32 + lane];
                float v2 = in[(size_t)s2 * 32 + lane];
                float v3 = in[(size_t)s3 * 32 + lane];
                a += c0 * v0 + c1 * v1 + c2 * v2 + c3 * v3;
            }
            for (; e < cnt; e++) {
                int s = sp[e]; float c = cp[e];
                a += c * in[(size_t)s * 32 + lane];
            }
            float d = g_dinv[n]; float d2 = d * d;
            a += d2 * in[(size_t)n * 32 + lane];
            tout[(size_t)n * 32 + lane] = a;
        }
    }
}

// ---------------- fused two-tower matmul + bias + relu (warp per node) -----
// Input row t[n] layout:
//   SHARED_IN: both towers read t[n, 0:DINH]               (row stride DINH)
//   else:      tower0 reads t[n, 0:DINH], tower1 t[n, DINH:2*DINH]
// out[n, 0:DOUTH]       = relu(t_mu  @ Wm + bm)
// out[n, DOUTH:2*DOUTH] = relu(t_log @ Wl + bl)
template<int DINH, int DOUTH, bool SHARED_IN>
__global__ void __launch_bounds__(256)
k_mm(const float* __restrict__ t,
     const float* __restrict__ Wm, const float* __restrict__ bm,
     const float* __restrict__ Wl, const float* __restrict__ bl,
     float* __restrict__ out)
{
    const int DOUT = 2 * DOUTH;
    const int R = DOUT / 32;
    const int IN_STRIDE = SHARED_IN ? DINH : 2 * DINH;
    __shared__ float Ws[2 * DINH * DOUTH];
    __shared__ float bs[DOUT];
    for (int i = threadIdx.x; i < DINH * DOUTH; i += blockDim.x) {
        Ws[i] = Wm[i];
        Ws[DINH * DOUTH + i] = Wl[i];
    }
    for (int i = threadIdx.x; i < DOUTH; i += blockDim.x) {
        bs[i] = bm[i];
        bs[DOUTH + i] = bl[i];
    }
    __syncthreads();
    int gwarp  = (blockIdx.x * blockDim.x + threadIdx.x) >> 5;
    int lane   = threadIdx.x & 31;
    int nwarps = (gridDim.x * blockDim.x) >> 5;

    // per-r constants (j = lane + 32*r): weight base + input-half base
    int woff[R], ioff[R];
    #pragma unroll
    for (int r = 0; r < R; r++) {
        int j = lane + 32 * r;
        int tower = (j >= DOUTH) ? 1 : 0;
        int jj = j - tower * DOUTH;
        woff[r] = tower * DINH * DOUTH + jj;
        ioff[r] = SHARED_IN ? 0 : tower * DINH;
    }

    for (int n = gwarp; n < N_NODES; n += nwarps) {
        float acc[R];
        #pragma unroll
        for (int r = 0; r < R; r++) acc[r] = bs[lane + 32 * r];
        const float* __restrict__ row = t + (size_t)n * IN_STRIDE;
        #pragma unroll
        for (int k = 0; k < DINH; k++) {
            #pragma unroll
            for (int r = 0; r < R; r++)
                acc[r] += row[ioff[r] + k] * Ws[woff[r] + k * DOUTH];
        }
        #pragma unroll
        for (int r = 0; r < R; r++)
            out[(size_t)n * DOUT + lane + 32 * r] = fmaxf(acc[r], 0.f);
    }
}

// ---------------- segmented mean pool (batch is sorted) --------------------
__global__ void k_pool(const float* __restrict__ a, const int* __restrict__ batch)
{
    int n0 = blockIdx.x * 64;
    if (n0 >= N_NODES) return;
    int j = threadIdx.x;            // 128 threads: one per feature dim
    int nend = min(n0 + 64, N_NODES);
    int gcur = batch[n0];
    float acc = 0.f, cacc = 0.f;
    for (int n = n0; n < nend; n++) {
        int g = batch[n];
        if (g != gcur) {
            atomicAdd(&g_pool[gcur * 128 + j], acc);
            if (j == 0) atomicAdd(&g_cnt[gcur], cacc);
            acc = 0.f; cacc = 0.f; gcur = g;
        }
        acc += a[(size_t)n * 128 + j];
        cacc += 1.f;
    }
    atomicAdd(&g_pool[gcur * 128 + j], acc);
    if (j == 0) atomicAdd(&g_cnt[gcur], cacc);
}

// ---------------- latent: mu/logvar means, reparameterized z ---------------
__global__ void k_latent(const float* __restrict__ eps, float* __restrict__ out)
{
    int tid = blockIdx.x * blockDim.x + threadIdx.x;
    if (tid >= N_GRAPHS * 64) return;
    int g = tid >> 6;
    int j = tid & 63;
    float cnt = fmaxf(g_cnt[g], 1.f);
    float mu = g_pool[g * 128 + j] / cnt;
    float lv = g_pool[g * 128 + 64 + j] / cnt;
    out[10240000 + tid] = mu;
    out[10240000 + 4096 + tid] = lv;
    g_z[tid] = mu + eps[tid] * expf(0.5f * lv);
}

// ---------------- decoder: sigmoid(z @ Wfc + bfc) --------------------------
__global__ void __launch_bounds__(256)
k_decode(const float* __restrict__ Wfc, const float* __restrict__ bfc,
         float* __restrict__ out)
{
    __shared__ float zs[N_GRAPHS * 64];
    for (int i = threadIdx.x; i < N_GRAPHS * 64; i += blockDim.x)
        zs[i] = g_z[i];
    __syncthreads();
    int j = blockIdx.x * blockDim.x + threadIdx.x;
    if (j >= 160000) return;
    float acc[N_GRAPHS];
    #pragma unroll
    for (int g = 0; g < N_GRAPHS; g++) acc[g] = 0.f;
    for (int k = 0; k < 64; k++) {
        float w = Wfc[(size_t)k * 160000 + j];
        #pragma unroll
        for (int g = 0; g < N_GRAPHS; g++)
            acc[g] += zs[g * 64 + k] * w;
    }
    float b = bfc[j];
    #pragma unroll
    for (int g = 0; g < N_GRAPHS; g++) {
        float v = acc[g] + b;
        out[(size_t)g * 160000 + j] = 1.f / (1.f + expf(-v));
    }
}

// ---------------- launch ---------------------------------------------------
extern "C" void kernel_launch(void* const* d_in, const int* in_sizes, int n_in,
                              void* d_out, int out_size)
{
    const float* x     = (const float*)d_in[0];
    const int*   ei    = (const int*)  d_in[1];
    const int*   batch = (const int*)  d_in[2];
    const float* W1m = (const float*)d_in[3];
    const float* b1m = (const float*)d_in[4];
    const float* W2m = (const float*)d_in[5];
    const float* b2m = (const float*)d_in[6];
    const float* W3m = (const float*)d_in[7];
    const float* b3m = (const float*)d_in[8];
    const float* W1l = (const float*)d_in[9];
    const float* b1l = (const float*)d_in[10];
    const float* W2l = (const float*)d_in[11];
    const float* b2l = (const float*)d_in[12];
    const float* W3l = (const float*)d_in[13];
    const float* b3l = (const float*)d_in[14];
    const float* Wfc = (const float*)d_in[15];
    const float* bfc = (const float*)d_in[16];
    const float* eps = (const float*)d_in[17];
    float* out = (float*)d_out;

    const int* src = ei;
    const int* dst = ei + N_EDGES;

    // structure prep
    k_zero<<<256, 256>>>();
    k_deg<<<2048, 256>>>(dst);
    k_scan1<<<SCAN_BLOCKS, SCAN_CHUNK>>>();
    k_scan23<<<SCAN_BLOCKS, SCAN_CHUNK>>>();
    k_fill<<<2048, 256>>>(src, dst);

    // layer 1: agg x[N,64] -> t ; mm (shared input) -> a[N,32]
    k_agg<64><<<12500, 256>>>(x, g_t);
    k_mm<64, 16, true><<<12500, 256>>>(g_t, W1m, b1m, W1l, b1l, g_a);

    // layer 2: agg a[N,32] -> t ; mm (split input 16+16) -> a[N,64]
    k_agg<32><<<12500, 256>>>(g_a, g_t);
    k_mm<16, 32, false><<<12500, 256>>>(g_t, W2m, b2m, W2l, b2l, g_a);

    // layer 3: agg a[N,64] -> t ; mm (split input 32+32) -> a[N,128]
    k_agg<64><<<12500, 256>>>(g_a, g_t);
    k_mm<32, 64, false><<<12500, 256>>>(g_t, W3m, b3m, W3l, b3l, g_a);

    // pool + latent + decode
    k_pool<<<(N_NODES + 63) / 64, 128>>>(g_a, batch);
    k_latent<<<16, 256>>>(eps, out);
    k_decode<<<(160000 + 255) / 256, 256>>>(Wfc, bfc, out);
}

// round 11
// speedup vs baseline: 2.2653x; 1.0017x over previous
#include <cuda_runtime.h>
#include <math.h>

#define N_NODES  100000
#define N_EDGES  3200000
#define N_GRAPHS 64
#define SCAN_CHUNK 512
#define SCAN_BLOCKS ((N_NODES + SCAN_CHUNK - 1) / SCAN_CHUNK)   // 196

// ---------------- scratch (device globals; zero-initialized at load) -------
// Mutable-state contract: g_deg, g_fill, g_flag, g_pool, g_cnt are ZERO at
// the start of every kernel_launch execution (zero-init at module load, and
// k_cleanup re-zeroes them at the end of each call). Everything else is
// fully overwritten before being read.
__device__ int   g_deg [N_NODES];
__device__ int   g_fill[N_NODES];
__device__ int   g_off [N_NODES];
__device__ int   g_bsum[SCAN_BLOCKS];
__device__ int   g_flag[SCAN_BLOCKS];
__device__ float g_dinv[N_NODES];
__device__ int   g_src [N_EDGES];
__device__ float g_coef[N_EDGES];
__device__ float g_t   [N_NODES * 64];    // aggregated inputs (pre-matmul)
__device__ float g_a   [N_NODES * 128];   // layer activations
__device__ float g_pool[N_GRAPHS * 128];
__device__ float g_cnt [N_GRAPHS];
__device__ float g_z   [N_GRAPHS * 64];

// ---------------- degree histogram (launch 0) -------------------------------
__global__ void k_deg(const int* __restrict__ dst)
{
    int tid = blockIdx.x * blockDim.x + threadIdx.x;
    int stride = gridDim.x * blockDim.x;
    for (int e = tid; e < N_EDGES; e += stride)
        atomicAdd(&g_deg[dst[e]], 1);
}

// ---------------- fused single-pass scan + dinv (launch 1) ------------------
// Decoupled aggregates: each block publishes its local sum, then sums all
// predecessors' aggregates (all 196 blocks are co-resident -> spin is safe).
__global__ void k_scan()
{
    __shared__ int s[SCAN_CHUNK];
    __shared__ int sb[256];
    int b = blockIdx.x;
    int t = threadIdx.x;
    int i = b * SCAN_CHUNK + t;
    int v = (i < N_NODES) ? g_deg[i] : 0;
    s[t] = v;
    __syncthreads();
    for (int off = 1; off < SCAN_CHUNK; off <<= 1) {
        int tmp = (t >= off) ? s[t - off] : 0;
        __syncthreads();
        s[t] += tmp;
        __syncthreads();
    }
    // publish block aggregate
    if (t == SCAN_CHUNK - 1) {
        g_bsum[b] = s[SCAN_CHUNK - 1];
        __threadfence();
        atomicExch(&g_flag[b], 1);
    }
    // gather predecessor aggregates (thread t handles predecessor t)
    int val = 0;
    if (t < 256) {
        if (t < b) {
            while (atomicAdd(&g_flag[t], 0) == 0) { }
            __threadfence();
            val = g_bsum[t];
        }
        sb[t] = val;
    }
    __syncthreads();
    for (int off = 128; off > 0; off >>= 1) {
        if (t < off) sb[t] += sb[t + off];
        __syncthreads();
    }
    int prefix = sb[0];
    if (i < N_NODES) {
        g_off[i] = prefix + s[t] - v;      // global exclusive offset
        g_dinv[i] = rsqrtf((float)g_deg[i] + 1.0f);
    }
}

// ---------------- CSR fill (launch 2) ---------------------------------------
__global__ void k_fill(const int* __restrict__ src, const int* __restrict__ dst)
{
    int tid = blockIdx.x * blockDim.x + threadIdx.x;
    int stride = gridDim.x * blockDim.x;
    for (int e = tid; e < N_EDGES; e += stride) {
        int s = src[e];
        int d = dst[e];
        int p = atomicAdd(&g_fill[d], 1);
        int idx = g_off[d] + p;
        g_src[idx]  = s;
        g_coef[idx] = g_dinv[s] * g_dinv[d];
    }
}

// ---------------- CSR gather aggregation, 4 warps per node ------------------
// t[n] = sum_{s in N(n)} coef * in[s] + dinv[n]^2 * in[n]
// Block: 256 threads = 8 warps = 2 nodes x 4 warps. Each warp covers a
// quarter of the node's edge list; partials reduced through shared memory.
template<int DIN>
__global__ void __launch_bounds__(256)
k_agg(const float* __restrict__ in, float* __restrict__ tout)
{
    const int WPN = 4;
    __shared__ float part[2][WPN][DIN];
    int wid  = threadIdx.x >> 5;
    int lane = threadIdx.x & 31;
    int ln   = wid / WPN;          // local node 0..1
    int wsub = wid & (WPN - 1);    // warp-within-node 0..3
    int n = blockIdx.x * 2 + ln;

    if (n < N_NODES) {
        int start = g_off[n];
        int cnt = ((n + 1 < N_NODES) ? g_off[n + 1] : N_EDGES) - start;
        int per = (cnt + WPN - 1) / WPN;
        int e0 = wsub * per;
        int e1 = min(e0 + per, cnt);
        const int*   __restrict__ sp = g_src  + start;
        const float* __restrict__ cp = g_coef + start;

        if (DIN == 64) {
            float ax = 0.f, ay = 0.f;
            int e = e0;
            for (; e + 4 <= e1; e += 4) {
                int s0 = sp[e], s1 = sp[e+1], s2 = sp[e+2], s3 = sp[e+3];
                float c0 = cp[e], c1 = cp[e+1], c2 = cp[e+2], c3 = cp[e+3];
                float2 v0 = *(const float2*)(in + (size_t)s0 * 64 + lane * 2);
                float2 v1 = *(const float2*)(in + (size_t)s1 * 64 + lane * 2);
                float2 v2 = *(const float2*)(in + (size_t)s2 * 64 + lane * 2);
                float2 v3 = *(const float2*)(in + (size_t)s3 * 64 + lane * 2);
                ax += c0 * v0.x; ay += c0 * v0.y;
                ax += c1 * v1.x; ay += c1 * v1.y;
                ax += c2 * v2.x; ay += c2 * v2.y;
                ax += c3 * v3.x; ay += c3 * v3.y;
            }
            for (; e < e1; e++) {
                int s = sp[e]; float c = cp[e];
                float2 v = *(const float2*)(in + (size_t)s * 64 + lane * 2);
                ax += c * v.x; ay += c * v.y;
            }
            part[ln][wsub][lane * 2]     = ax;
            part[ln][wsub][lane * 2 + 1] = ay;
        } else { // DIN == 32
            float a = 0.f;
            int e = e0;
            for (; e + 4 <= e1; e += 4) {
                int s0 = sp[e], s1 = sp[e+1], s2 = sp[e+2], s3 = sp[e+3];
                float c0 = cp[e], c1 = cp[e+1], c2 = cp[e+2], c3 = cp[e+3];
                a += c0 * in[(size_t)s0 * 32 + lane];
                a += c1 * in[(size_t)s1 * 32 + lane];
                a += c2 * in[(size_t)s2 * 32 + lane];
                a += c3 * in[(size_t)s3 * 32 + lane];
            }
            for (; e < e1; e++)
                a += cp[e] * in[(size_t)sp[e] * 32 + lane];
            part[ln][wsub][lane] = a;
        }
    }
    __syncthreads();

    // warps 0 and 4 (wsub==0) finalize their node
    if (wsub == 0 && n < N_NODES) {
        float d = g_dinv[n];
        float d2 = d * d;
        if (DIN == 64) {
            int j0 = lane * 2, j1 = lane * 2 + 1;
            float ax = part[ln][0][j0] + part[ln][1][j0] + part[ln][2][j0] + part[ln][3][j0];
            float ay = part[ln][0][j1] + part[ln][1][j1] + part[ln][2][j1] + part[ln][3][j1];
            float2 vn = *(const float2*)(in + (size_t)n * 64 + j0);
            ax += d2 * vn.x; ay += d2 * vn.y;
            *(float2*)(tout + (size_t)n * 64 + j0) = make_float2(ax, ay);
        } else {
            float a = part[ln][0][lane] + part[ln][1][lane] + part[ln][2][lane] + part[ln][3][lane];
            a += d2 * in[(size_t)n * 32 + lane];
            tout[(size_t)n * 32 + lane] = a;
        }
    }
}

// ---------------- fused two-tower matmul + bias + relu (warp per node) -----
template<int DINH, int DOUTH, bool SHARED_IN>
__global__ void __launch_bounds__(256)
k_mm(const float* __restrict__ t,
     const float* __restrict__ Wm, const float* __restrict__ bm,
     const float* __restrict__ Wl, const float* __restrict__ bl,
     float* __restrict__ out)
{
    const int DOUT = 2 * DOUTH;
    const int R = DOUT / 32;
    const int IN_STRIDE = SHARED_IN ? DINH : 2 * DINH;
    __shared__ float Ws[2 * DINH * DOUTH];
    __shared__ float bs[DOUT];
    for (int i = threadIdx.x; i < DINH * DOUTH; i += blockDim.x) {
        Ws[i] = Wm[i];
        Ws[DINH * DOUTH + i] = Wl[i];
    }
    for (int i = threadIdx.x; i < DOUTH; i += blockDim.x) {
        bs[i] = bm[i];
        bs[DOUTH + i] = bl[i];
    }
    __syncthreads();
    int gwarp  = (blockIdx.x * blockDim.x + threadIdx.x) >> 5;
    int lane   = threadIdx.x & 31;
    int nwarps = (gridDim.x * blockDim.x) >> 5;

    int woff[R], ioff[R];
    #pragma unroll
    for (int r = 0; r < R; r++) {
        int j = lane + 32 * r;
        int tower = (j >= DOUTH) ? 1 : 0;
        int jj = j - tower * DOUTH;
        woff[r] = tower * DINH * DOUTH + jj;
        ioff[r] = SHARED_IN ? 0 : tower * DINH;
    }

    for (int n = gwarp; n < N_NODES; n += nwarps) {
        float acc[R];
        #pragma unroll
        for (int r = 0; r < R; r++) acc[r] = bs[lane + 32 * r];
        const float* __restrict__ row = t + (size_t)n * IN_STRIDE;
        #pragma unroll
        for (int k = 0; k < DINH; k++) {
            #pragma unroll
            for (int r = 0; r < R; r++)
                acc[r] += row[ioff[r] + k] * Ws[woff[r] + k * DOUTH];
        }
        #pragma unroll
        for (int r = 0; r < R; r++)
            out[(size_t)n * DOUT + lane + 32 * r] = fmaxf(acc[r], 0.f);
    }
}

// ---------------- segmented mean pool (batch is sorted) --------------------
__global__ void k_pool(const float* __restrict__ a, const int* __restrict__ batch)
{
    int n0 = blockIdx.x * 64;
    if (n0 >= N_NODES) return;
    int j = threadIdx.x;            // 128 threads: one per feature dim
    int nend = min(n0 + 64, N_NODES);
    int gcur = batch[n0];
    float acc = 0.f, cacc = 0.f;
    for (int n = n0; n < nend; n++) {
        int g = batch[n];
        if (g != gcur) {
            atomicAdd(&g_pool[gcur * 128 + j], acc);
            if (j == 0) atomicAdd(&g_cnt[gcur], cacc);
            acc = 0.f; cacc = 0.f; gcur = g;
        }
        acc += a[(size_t)n * 128 + j];
        cacc += 1.f;
    }
    atomicAdd(&g_pool[gcur * 128 + j], acc);
    if (j == 0) atomicAdd(&g_cnt[gcur], cacc);
}

// ---------------- latent: mu/logvar means, reparameterized z ---------------
__global__ void k_latent(const float* __restrict__ eps, float* __restrict__ out)
{
    int tid = blockIdx.x * blockDim.x + threadIdx.x;
    if (tid >= N_GRAPHS * 64) return;
    int g = tid >> 6;
    int j = tid & 63;
    float cnt = fmaxf(g_cnt[g], 1.f);
    float mu = g_pool[g * 128 + j] / cnt;
    float lv = g_pool[g * 128 + 64 + j] / cnt;
    out[10240000 + tid] = mu;
    out[10240000 + 4096 + tid] = lv;
    g_z[tid] = mu + eps[tid] * expf(0.5f * lv);
}

// ---------------- decoder: sigmoid(z @ Wfc + bfc) --------------------------
__global__ void __launch_bounds__(256)
k_decode(const float* __restrict__ Wfc, const float* __restrict__ bfc,
         float* __restrict__ out)
{
    __shared__ float zs[N_GRAPHS * 64];
    for (int i = threadIdx.x; i < N_GRAPHS * 64; i += blockDim.x)
        zs[i] = g_z[i];
    __syncthreads();
    int j = blockIdx.x * blockDim.x + threadIdx.x;
    if (j >= 160000) return;
    float acc[N_GRAPHS];
    #pragma unroll
    for (int g = 0; g < N_GRAPHS; g++) acc[g] = 0.f;
    for (int k = 0; k < 64; k++) {
        float w = Wfc[(size_t)k * 160000 + j];
        #pragma unroll
        for (int g = 0; g < N_GRAPHS; g++)
            acc[g] += zs[g * 64 + k] * w;
    }
    float b = bfc[j];
    #pragma unroll
    for (int g = 0; g < N_GRAPHS; g++) {
        float v = acc[g] + b;
        out[(size_t)g * 160000 + j] = 1.f / (1.f + expf(-v));
    }
}

// ---------------- tail: restore mutable state for next replay --------------
__global__ void k_cleanup()
{
    int tid = blockIdx.x * blockDim.x + threadIdx.x;
    int stride = gridDim.x * blockDim.x;
    for (int i = tid; i < N_NODES; i += stride) { g_deg[i] = 0; g_fill[i] = 0; }
    for (int i = tid; i < SCAN_BLOCKS; i += stride) g_flag[i] = 0;
    for (int i = tid; i < N_GRAPHS * 128; i += stride) g_pool[i] = 0.f;
    for (int i = tid; i < N_GRAPHS; i += stride) g_cnt[i] = 0.f;
}

// ---------------- launch ---------------------------------------------------
extern "C" void kernel_launch(void* const* d_in, const int* in_sizes, int n_in,
                              void* d_out, int out_size)
{
    const float* x     = (const float*)d_in[0];
    const int*   ei    = (const int*)  d_in[1];
    const int*   batch = (const int*)  d_in[2];
    const float* W1m = (const float*)d_in[3];
    const float* b1m = (const float*)d_in[4];
    const float* W2m = (const float*)d_in[5];
    const float* b2m = (const float*)d_in[6];
    const float* W3m = (const float*)d_in[7];
    const float* b3m = (const float*)d_in[8];
    const float* W1l = (const float*)d_in[9];
    const float* b1l = (const float*)d_in[10];
    const float* W2l = (const float*)d_in[11];
    const float* b2l = (const float*)d_in[12];
    const float* W3l = (const float*)d_in[13];
    const float* b3l = (const float*)d_in[14];
    const float* Wfc = (const float*)d_in[15];
    const float* bfc = (const float*)d_in[16];
    const float* eps = (const float*)d_in[17];
    float* out = (float*)d_out;

    const int* src = ei;
    const int* dst = ei + N_EDGES;

    // prep (launch indices 0..2)
    k_deg <<<2048, 256>>>(dst);
    k_scan<<<SCAN_BLOCKS, SCAN_CHUNK>>>();
    k_fill<<<2048, 256>>>(src, dst);

    // layer 1 (k_agg<64> at launch index 3 -> gets the ncu profile)
    k_agg<64><<<(N_NODES + 1) / 2, 256>>>(x, g_t);
    k_mm<64, 16, true><<<12500, 256>>>(g_t, W1m, b1m, W1l, b1l, g_a);

    // layer 2
    k_agg<32><<<(N_NODES + 1) / 2, 256>>>(g_a, g_t);
    k_mm<16, 32, false><<<12500, 256>>>(g_t, W2m, b2m, W2l, b2l, g_a);

    // layer 3
    k_agg<64><<<(N_NODES + 1) / 2, 256>>>(g_a, g_t);
    k_mm<32, 64, false><<<12500, 256>>>(g_t, W3m, b3m, W3l, b3l, g_a);

    // pool + latent + decode
    k_pool<<<(N_NODES + 63) / 64, 128>>>(g_a, batch);
    k_latent<<<16, 256>>>(eps, out);
    k_decode<<<(160000 + 255) / 256, 256>>>(Wfc, bfc, out);

    // restore mutable state for the next (deterministic) replay
    k_cleanup<<<256, 256>>>();
}